// round 2
// baseline (speedup 1.0000x reference)
#include <cuda_runtime.h>
#include <stdint.h>

// ============================================================================
// ImpulseNoise — bit-exact JAX (threefry_partitionable=True, the modern
// default) salt & pepper noise. key=42, amount=0.09, salt_vs_pepper=0.5.
//
//   key = (0, 42)
//   split (foldlike): k_flip = tf20(key, (0,0));  k_salt = tf20(key, (0,1))
//          (both output words of ONE hash form each child key)
//   random_bits(32) for element i: b = tf20(k, (hi32(i), lo32(i))),
//          bits = b.x0 ^ b.x1.   (hi32(i)=0 since N < 2^32)
//   uniform u = bitcast((bits>>9)|0x3f800000) - 1  =  (bits>>9) * 2^-23 exact
//   u <= 0.09f  <=>  bits <= (754974<<9)|511   (0.09f*2^23 = 754974.75)
//   u <= 0.5    <=>  bits <= (4194304<<9)|511 = 0x800001FF
// ============================================================================

struct U2c { unsigned a, b; };

constexpr U2c threefry20_host(unsigned k0, unsigned k1, unsigned x0, unsigned x1) {
    unsigned ks2 = k0 ^ k1 ^ 0x1BD11BDAu;
    x0 += k0; x1 += k1;
#define TFR_H(r) { x0 += x1; x1 = (x1 << (r)) | (x1 >> (32 - (r))); x1 ^= x0; }
    TFR_H(13) TFR_H(15) TFR_H(26) TFR_H(6)
    x0 += k1;  x1 += ks2 + 1u;
    TFR_H(17) TFR_H(29) TFR_H(16) TFR_H(24)
    x0 += ks2; x1 += k0 + 2u;
    TFR_H(13) TFR_H(15) TFR_H(26) TFR_H(6)
    x0 += k0;  x1 += k1 + 3u;
    TFR_H(17) TFR_H(29) TFR_H(16) TFR_H(24)
    x0 += k1;  x1 += ks2 + 4u;
    TFR_H(13) TFR_H(15) TFR_H(26) TFR_H(6)
    x0 += ks2; x1 += k0 + 5u;
#undef TFR_H
    return U2c{x0, x1};
}

// Partitionable (foldlike) split of key (0,42) over shape (2,):
// counts = hi/lo of 64-bit iota [0,1] -> pairs (0,0) and (0,1).
constexpr U2c KFLIP = threefry20_host(0u, 42u, 0u, 0u);
constexpr U2c KSALT = threefry20_host(0u, 42u, 0u, 1u);

constexpr unsigned N_TOTAL = 64u * 3u * 512u * 512u;  // 50331648

// Integer thresholds equivalent to the float comparisons (exact).
constexpr unsigned FLIP_T = (754974u << 9) | 511u;    // u <= 0.09f
constexpr unsigned SALT_T = (4194304u << 9) | 511u;   // u <= 0.5f  (0x800001FF)

// Threefry-2x32-20 with key immediates; counter = (0, i); returns x0^x1.
#define TFR(r) { x0 += x1; x1 = __funnelshift_l(x1, x1, (r)); x1 ^= x0; }
template <unsigned K0, unsigned K1>
__device__ __forceinline__ unsigned tf20_fold(unsigned i) {
    constexpr unsigned KS2 = K0 ^ K1 ^ 0x1BD11BDAu;
    unsigned x0 = K0;        // 0 + K0
    unsigned x1 = i + K1;
    TFR(13) TFR(15) TFR(26) TFR(6)
    x0 += K1;  x1 += KS2 + 1u;
    TFR(17) TFR(29) TFR(16) TFR(24)
    x0 += KS2; x1 += K0 + 2u;
    TFR(13) TFR(15) TFR(26) TFR(6)
    x0 += K0;  x1 += K1 + 3u;
    TFR(17) TFR(29) TFR(16) TFR(24)
    x0 += K1;  x1 += KS2 + 4u;
    TFR(13) TFR(15) TFR(26) TFR(6)
    x0 += KS2; x1 += K0 + 5u;
    return x0 ^ x1;
}
#undef TFR

__device__ __forceinline__ float apply_noise(unsigned i, float v) {
    unsigned bf = tf20_fold<KFLIP.a, KFLIP.b>(i);
    unsigned bs = tf20_fold<KSALT.a, KSALT.b>(i);
    bool flipped = (bf <= FLIP_T);
    bool salted  = (bs <= SALT_T);
    return flipped ? (salted ? 1.0f : 0.0f) : v;
}

// 4 consecutive elements per thread, float4 I/O.
__global__ void __launch_bounds__(256)
impulse_noise_kernel(const float* __restrict__ img, float* __restrict__ out) {
    unsigned t = blockIdx.x * 256u + threadIdx.x;
    unsigned i = 4u * t;

    float4 v = *reinterpret_cast<const float4*>(img + i);
    float4 o;
    o.x = apply_noise(i,      v.x);
    o.y = apply_noise(i + 1u, v.y);
    o.z = apply_noise(i + 2u, v.z);
    o.w = apply_noise(i + 3u, v.w);
    *reinterpret_cast<float4*>(out + i) = o;
}

extern "C" void kernel_launch(void* const* d_in, const int* in_sizes, int n_in,
                              void* d_out, int out_size) {
    const float* img = (const float*)d_in[0];
    float* out = (float*)d_out;
    constexpr unsigned threads = N_TOTAL / 4u;   // 12582912
    constexpr unsigned blocks  = threads / 256u; // 49152
    impulse_noise_kernel<<<blocks, 256>>>(img, out);
}

// round 3
// speedup vs baseline: 1.5109x; 1.5109x over previous
#include <cuda_runtime.h>
#include <stdint.h>

// ============================================================================
// ImpulseNoise — bit-exact JAX (threefry_partitionable) salt & pepper.
// key=(0,42); k_flip = tf20(key,(0,0)); k_salt = tf20(key,(0,1))
// bits(i) = fold(tf20(k, (0, i)));  u = (bits>>9)*2^-23
// u <= 0.09f  <=>  bits <= (754974<<9)|511     (verified rel_err=0 in R2)
// u <= 0.5    <=>  bits <= 0x800001FF
//
// R3 optimizations:
//  - all hash adds forced to IMAD (fma pipe) via runtime `one` multiplier
//    (alu pipe was 96.9% saturated; SHF/LOP3 are alu-only, adds are not)
//  - salt hash computed only for flipped pixels via warp ballot-compaction:
//    warp owns 256 elems, ~23 expected flips -> ~1 warp-wide salt pass
//    instead of 256 salt hashes. Owners store raw values (STG.128), then
//    __syncwarp() fence, then compacted lanes overwrite flips with 1.0/0.0.
// ============================================================================

struct U2c { unsigned a, b; };

constexpr U2c threefry20_host(unsigned k0, unsigned k1, unsigned x0, unsigned x1) {
    unsigned ks2 = k0 ^ k1 ^ 0x1BD11BDAu;
    x0 += k0; x1 += k1;
#define TFR_H(r) { x0 += x1; x1 = (x1 << (r)) | (x1 >> (32 - (r))); x1 ^= x0; }
    TFR_H(13) TFR_H(15) TFR_H(26) TFR_H(6)
    x0 += k1;  x1 += ks2 + 1u;
    TFR_H(17) TFR_H(29) TFR_H(16) TFR_H(24)
    x0 += ks2; x1 += k0 + 2u;
    TFR_H(13) TFR_H(15) TFR_H(26) TFR_H(6)
    x0 += k0;  x1 += k1 + 3u;
    TFR_H(17) TFR_H(29) TFR_H(16) TFR_H(24)
    x0 += k1;  x1 += ks2 + 4u;
    TFR_H(13) TFR_H(15) TFR_H(26) TFR_H(6)
    x0 += ks2; x1 += k0 + 5u;
#undef TFR_H
    return U2c{x0, x1};
}

constexpr U2c KFLIP = threefry20_host(0u, 42u, 0u, 0u);
constexpr U2c KSALT = threefry20_host(0u, 42u, 0u, 1u);

constexpr unsigned N_TOTAL = 64u * 3u * 512u * 512u;   // 50331648
constexpr unsigned FLIP_T  = (754974u << 9) | 511u;    // u <= 0.09f
constexpr unsigned SALT_T  = 0x800001FFu;              // u <= 0.5f

// Threefry-2x32-20, counter (0, i), fold x0^x1. All adds as IMAD via `one`.
#define ADD1(d, a, b) (d) = (a) * one + (b)
#define TFR(r) { ADD1(x0, x0, x1); x1 = __funnelshift_l(x1, x1, (r)); x1 ^= x0; }
template <unsigned K0, unsigned K1>
__device__ __forceinline__ unsigned tf20_fold(unsigned i, unsigned one) {
    constexpr unsigned KS2 = K0 ^ K1 ^ 0x1BD11BDAu;
    unsigned x0 = K0;
    unsigned x1; ADD1(x1, i, K1);
    TFR(13) TFR(15) TFR(26) TFR(6)
    ADD1(x0, x0, K1);  ADD1(x1, x1, KS2 + 1u);
    TFR(17) TFR(29) TFR(16) TFR(24)
    ADD1(x0, x0, KS2); ADD1(x1, x1, K0 + 2u);
    TFR(13) TFR(15) TFR(26) TFR(6)
    ADD1(x0, x0, K0);  ADD1(x1, x1, K1 + 3u);
    TFR(17) TFR(29) TFR(16) TFR(24)
    ADD1(x0, x0, K1);  ADD1(x1, x1, KS2 + 4u);
    TFR(13) TFR(15) TFR(26) TFR(6)
    ADD1(x0, x0, KS2); ADD1(x1, x1, K0 + 5u);
    return x0 ^ x1;
}
#undef TFR
#undef ADD1

// 8 elements per thread; warp covers 256 consecutive elements.
// Lane L owns elems base+4L+s (s=0..3) and base+128+4L+s (s=4..7).
__global__ void __launch_bounds__(256)
impulse_noise_kernel(const float* __restrict__ img, float* __restrict__ out,
                     unsigned one) {
    unsigned gwarp = (blockIdx.x * 256u + threadIdx.x) >> 5;
    unsigned lane  = threadIdx.x & 31u;
    unsigned base  = gwarp * 256u;
    unsigned i0 = base + 4u * lane;
    unsigned i1 = base + 128u + 4u * lane;

    float4 v0 = *reinterpret_cast<const float4*>(img + i0);
    float4 v1 = *reinterpret_cast<const float4*>(img + i1);

    // Mandatory flip hashes (8 independent chains -> good ILP).
    bool fl[8];
#pragma unroll
    for (int s = 0; s < 4; ++s)
        fl[s] = tf20_fold<KFLIP.a, KFLIP.b>(i0 + (unsigned)s, one) <= FLIP_T;
#pragma unroll
    for (int s = 0; s < 4; ++s)
        fl[4 + s] = tf20_fold<KFLIP.a, KFLIP.b>(i1 + (unsigned)s, one) <= FLIP_T;

    // Owners store raw values everywhere; flipped slots overwritten below.
    *reinterpret_cast<float4*>(out + i0) = v0;
    *reinterpret_cast<float4*>(out + i1) = v1;

    // Warp-uniform flip masks + prefix counts.
    unsigned m[8], cum[9];
    cum[0] = 0;
#pragma unroll
    for (int s = 0; s < 8; ++s) {
        m[s] = __ballot_sync(0xFFFFFFFFu, fl[s]);
        cum[s + 1] = cum[s] + (unsigned)__popc(m[s]);
    }
    unsigned nf = cum[8];

    // Order owner stores before the compacted overwrites (warp-scope fence).
    __syncwarp();

    // Compacted salt passes: 32 flips served per pass (usually exactly 1 pass).
    for (unsigned start = 0; start < nf; start += 32u) {
        unsigned r = start + lane;
        if (r < nf) {
            // Select which mask word holds the r-th set flip (SEL chain, no spills).
            unsigned mm = m[0], rbase = 0u, eoff = 0u;
#pragma unroll
            for (int w = 1; w < 8; ++w) {
                if (r >= cum[w]) {
                    mm = m[w];
                    rbase = cum[w];
                    eoff = (w < 4) ? (unsigned)w : (unsigned)w + 124u;
                }
            }
            unsigned rr = r - rbase;
            // rr-th set bit of mm (binary search by popc).
            unsigned pos = 0u, c;
            c = (unsigned)__popc(mm & 0xFFFFu); if (rr >= c) { rr -= c; pos += 16u; mm >>= 16; }
            c = (unsigned)__popc(mm & 0xFFu);   if (rr >= c) { rr -= c; pos += 8u;  mm >>= 8; }
            c = (unsigned)__popc(mm & 0xFu);    if (rr >= c) { rr -= c; pos += 4u;  mm >>= 4; }
            c = (unsigned)__popc(mm & 0x3u);    if (rr >= c) { rr -= c; pos += 2u;  mm >>= 2; }
            c = mm & 1u;                        if (rr >= c) { pos += 1u; }

            unsigned gi = base + 4u * pos + eoff;
            unsigned bs = tf20_fold<KSALT.a, KSALT.b>(gi, one);
            out[gi] = (bs <= SALT_T) ? 1.0f : 0.0f;
        }
    }
}

extern "C" void kernel_launch(void* const* d_in, const int* in_sizes, int n_in,
                              void* d_out, int out_size) {
    const float* img = (const float*)d_in[0];
    float* out = (float*)d_out;
    constexpr unsigned threads = N_TOTAL / 8u;    // 6291456
    constexpr unsigned blocks  = threads / 256u;  // 24576
    impulse_noise_kernel<<<blocks, 256>>>(img, out, 1u);
}

// round 4
// speedup vs baseline: 1.5200x; 1.0060x over previous
#include <cuda_runtime.h>
#include <stdint.h>

// ============================================================================
// ImpulseNoise — bit-exact JAX (threefry_partitionable) salt & pepper.
// key=(0,42); k_flip = tf20(key,(0,0)); k_salt = tf20(key,(0,1))
// bits(i) = fold(tf20(k, (0, i)));  u = (bits>>9)*2^-23
// u <= 0.09f  <=>  bits <= (754974<<9)|511     (rel_err=0 verified R2/R3)
// u <= 0.5    <=>  bits <= 0x800001FF
//
// R4: every hash add forced onto the FMA pipe via inline-PTX mad.lo.u32
// with runtime multiplier `one` (R3's C++ a*one+b only half-converted:
// fma=30.5% vs expected ~60%). alu pipe (saturated at 87.8%) drops to its
// structural floor of 20 SHF + 21 LOP3 per hash.
// Salt hashes remain warp-ballot-compacted (~0.09 hashes/elem).
// ============================================================================

struct U2c { unsigned a, b; };

constexpr U2c threefry20_host(unsigned k0, unsigned k1, unsigned x0, unsigned x1) {
    unsigned ks2 = k0 ^ k1 ^ 0x1BD11BDAu;
    x0 += k0; x1 += k1;
#define TFR_H(r) { x0 += x1; x1 = (x1 << (r)) | (x1 >> (32 - (r))); x1 ^= x0; }
    TFR_H(13) TFR_H(15) TFR_H(26) TFR_H(6)
    x0 += k1;  x1 += ks2 + 1u;
    TFR_H(17) TFR_H(29) TFR_H(16) TFR_H(24)
    x0 += ks2; x1 += k0 + 2u;
    TFR_H(13) TFR_H(15) TFR_H(26) TFR_H(6)
    x0 += k0;  x1 += k1 + 3u;
    TFR_H(17) TFR_H(29) TFR_H(16) TFR_H(24)
    x0 += k1;  x1 += ks2 + 4u;
    TFR_H(13) TFR_H(15) TFR_H(26) TFR_H(6)
    x0 += ks2; x1 += k0 + 5u;
#undef TFR_H
    return U2c{x0, x1};
}

constexpr U2c KFLIP = threefry20_host(0u, 42u, 0u, 0u);
constexpr U2c KSALT = threefry20_host(0u, 42u, 0u, 1u);

constexpr unsigned N_TOTAL = 64u * 3u * 512u * 512u;   // 50331648
constexpr unsigned FLIP_T  = (754974u << 9) | 511u;    // u <= 0.09f
constexpr unsigned SALT_T  = 0x800001FFu;              // u <= 0.5f

// --- adds forced to IMAD (fma pipe): d = a*one + b -------------------------
__device__ __forceinline__ unsigned madr(unsigned a, unsigned one, unsigned b) {
    unsigned d;
    asm("mad.lo.u32 %0, %1, %2, %3;" : "=r"(d) : "r"(a), "r"(one), "r"(b));
    return d;
}
template <unsigned IMM>
__device__ __forceinline__ unsigned madi(unsigned a, unsigned one) {
    unsigned d;
    asm("mad.lo.u32 %0, %1, %2, %3;" : "=r"(d) : "r"(a), "r"(one), "n"(IMM));
    return d;
}

// Threefry-2x32-20, counter (0, i), returns x0^x1. 31 IMADs + 20 SHF + 21 LOP3.
#define TFR(r) { x0 = madr(x0, one, x1); x1 = __funnelshift_l(x1, x1, (r)); x1 ^= x0; }
template <unsigned K0, unsigned K1>
__device__ __forceinline__ unsigned tf20_fold(unsigned i, unsigned one) {
    constexpr unsigned KS2 = K0 ^ K1 ^ 0x1BD11BDAu;
    unsigned x1 = madi<K1>(i, one);
    // round 1 with x0 initial = K0 folded as immediate: x0 = x1*one + K0
    unsigned x0 = madi<K0>(x1, one);
    x1 = __funnelshift_l(x1, x1, 13); x1 ^= x0;
    TFR(15) TFR(26) TFR(6)
    x0 = madi<K1>(x0, one);        x1 = madi<KS2 + 1u>(x1, one);
    TFR(17) TFR(29) TFR(16) TFR(24)
    x0 = madi<KS2>(x0, one);       x1 = madi<K0 + 2u>(x1, one);
    TFR(13) TFR(15) TFR(26) TFR(6)
    x0 = madi<K0>(x0, one);        x1 = madi<K1 + 3u>(x1, one);
    TFR(17) TFR(29) TFR(16) TFR(24)
    x0 = madi<K1>(x0, one);        x1 = madi<KS2 + 4u>(x1, one);
    TFR(13) TFR(15) TFR(26) TFR(6)
    x0 = madi<KS2>(x0, one);       x1 = madi<K0 + 5u>(x1, one);
    return x0 ^ x1;
}
#undef TFR

// 8 elements per thread; warp covers 256 consecutive elements.
__global__ void __launch_bounds__(256)
impulse_noise_kernel(const float* __restrict__ img, float* __restrict__ out,
                     unsigned one) {
    unsigned gwarp = (blockIdx.x * 256u + threadIdx.x) >> 5;
    unsigned lane  = threadIdx.x & 31u;
    unsigned base  = gwarp * 256u;
    unsigned i0 = base + 4u * lane;
    unsigned i1 = base + 128u + 4u * lane;

    float4 v0 = *reinterpret_cast<const float4*>(img + i0);
    float4 v1 = *reinterpret_cast<const float4*>(img + i1);

    // Mandatory flip hashes (8 independent chains for ILP).
    bool fl[8];
#pragma unroll
    for (int s = 0; s < 4; ++s)
        fl[s] = tf20_fold<KFLIP.a, KFLIP.b>(i0 + (unsigned)s, one) <= FLIP_T;
#pragma unroll
    for (int s = 0; s < 4; ++s)
        fl[4 + s] = tf20_fold<KFLIP.a, KFLIP.b>(i1 + (unsigned)s, one) <= FLIP_T;

    // Owners store raw values; flipped slots overwritten after the fence.
    *reinterpret_cast<float4*>(out + i0) = v0;
    *reinterpret_cast<float4*>(out + i1) = v1;

    // Warp-uniform flip masks + prefix counts.
    unsigned m[8], cum[9];
    cum[0] = 0;
#pragma unroll
    for (int s = 0; s < 8; ++s) {
        m[s] = __ballot_sync(0xFFFFFFFFu, fl[s]);
        cum[s + 1] = cum[s] + (unsigned)__popc(m[s]);
    }
    unsigned nf = cum[8];

    __syncwarp();  // owner stores happen-before compacted overwrites

    // Compacted salt passes: 32 flips served per pass (~1 pass typical).
    for (unsigned start = 0; start < nf; start += 32u) {
        unsigned r = start + lane;
        if (r < nf) {
            unsigned mm = m[0], rbase = 0u, eoff = 0u;
#pragma unroll
            for (int w = 1; w < 8; ++w) {
                if (r >= cum[w]) {
                    mm = m[w];
                    rbase = cum[w];
                    eoff = (w < 4) ? (unsigned)w : (unsigned)w + 124u;
                }
            }
            unsigned rr = r - rbase;
            unsigned pos = 0u, c;
            c = (unsigned)__popc(mm & 0xFFFFu); if (rr >= c) { rr -= c; pos += 16u; mm >>= 16; }
            c = (unsigned)__popc(mm & 0xFFu);   if (rr >= c) { rr -= c; pos += 8u;  mm >>= 8; }
            c = (unsigned)__popc(mm & 0xFu);    if (rr >= c) { rr -= c; pos += 4u;  mm >>= 4; }
            c = (unsigned)__popc(mm & 0x3u);    if (rr >= c) { rr -= c; pos += 2u;  mm >>= 2; }
            c = mm & 1u;                        if (rr >= c) { pos += 1u; }

            unsigned gi = base + 4u * pos + eoff;
            unsigned bs = tf20_fold<KSALT.a, KSALT.b>(gi, one);
            out[gi] = (bs <= SALT_T) ? 1.0f : 0.0f;
        }
    }
}

extern "C" void kernel_launch(void* const* d_in, const int* in_sizes, int n_in,
                              void* d_out, int out_size) {
    const float* img = (const float*)d_in[0];
    float* out = (float*)d_out;
    constexpr unsigned threads = N_TOTAL / 8u;    // 6291456
    constexpr unsigned blocks  = threads / 256u;  // 24576
    impulse_noise_kernel<<<blocks, 256>>>(img, out, 1u);
}